// round 1
// baseline (speedup 1.0000x reference)
#include <cuda_runtime.h>
#include <cuda_bf16.h>
#include <stdint.h>

#define BATCH   64
#define NPB     16384
#define KSEL    1000
#define NCLS    80
#define NBIN    4096
#define SORTN   2048

typedef unsigned long long u64;

// scratch: selected local indices per batch
__device__ int g_topidx[BATCH * KSEL];

extern __shared__ unsigned char smem_raw[];

// Find the bin (scanning from the highest bin down) where the cumulative count
// first reaches Kneed. Writes bin and the count strictly above it.
__device__ __forceinline__ void find_thresh(
    const unsigned* hist, unsigned* scanb, unsigned Kneed,
    unsigned* out_bin, unsigned* out_above, int tid)
{
    int base = NBIN - 1 - 4 * tid;             // 4 descending bins per thread
    unsigned c0 = hist[base],     c1 = hist[base - 1];
    unsigned c2 = hist[base - 2], c3 = hist[base - 3];
    unsigned tsum = c0 + c1 + c2 + c3;
    scanb[tid] = tsum;
    __syncthreads();
    // Hillis-Steele inclusive scan over 1024 partials
    for (int d = 1; d < 1024; d <<= 1) {
        unsigned v = (tid >= d) ? scanb[tid - d] : 0u;
        __syncthreads();
        scanb[tid] += v;
        __syncthreads();
    }
    unsigned run = scanb[tid] - tsum;          // exclusive prefix (higher bins)
    if (run < Kneed && run + c0 >= Kneed) { *out_bin = (unsigned)base;     *out_above = run; }
    run += c0;
    if (run < Kneed && run + c1 >= Kneed) { *out_bin = (unsigned)base - 1; *out_above = run; }
    run += c1;
    if (run < Kneed && run + c2 >= Kneed) { *out_bin = (unsigned)base - 2; *out_above = run; }
    run += c2;
    if (run < Kneed && run + c3 >= Kneed) { *out_bin = (unsigned)base - 3; *out_above = run; }
    __syncthreads();
}

__global__ void __launch_bounds__(1024, 1)
topk_kernel(const float* __restrict__ scores)
{
    const int b   = blockIdx.x;
    const int tid = threadIdx.x;

    float*    sfg   = (float*)smem_raw;                         // 16384 f32 = 64 KB
    unsigned* hist  = (unsigned*)(sfg + NPB);                   // 4096 u32  = 16 KB
    unsigned* scanb = hist + NBIN;                              // 1024 u32  = 4 KB
    u64*      cand  = (u64*)(scanb + 1024);                     // 2048 u64  = 16 KB (offset 86016, 8B aligned)

    __shared__ unsigned s_bin1, s_above1, s_bin2, s_above2, s_ncand;

    // 1) load fg = 1 - scores[:, 0] for this batch segment
    const float* col = scores + (size_t)b * NPB * NCLS;
    #pragma unroll 4
    for (int i = tid; i < NPB; i += 1024)
        sfg[i] = 1.0f - col[(size_t)i * NCLS];

    for (int i = tid; i < NBIN; i += 1024) hist[i] = 0u;
    __syncthreads();

    // 2) level-1 histogram: top 12 bits of float bits (positive floats -> monotone)
    for (int i = tid; i < NPB; i += 1024) {
        unsigned u = __float_as_uint(sfg[i]);
        atomicAdd(&hist[u >> 20], 1u);
    }
    __syncthreads();
    find_thresh(hist, scanb, KSEL, &s_bin1, &s_above1, tid);
    unsigned bin1   = s_bin1;
    unsigned above1 = s_above1;

    // 3) level-2 histogram: next 12 bits, among elements in bin1 only
    for (int i = tid; i < NBIN; i += 1024) hist[i] = 0u;
    __syncthreads();
    for (int i = tid; i < NPB; i += 1024) {
        unsigned u = __float_as_uint(sfg[i]);
        if ((u >> 20) == bin1) atomicAdd(&hist[(u >> 8) & 0xFFFu], 1u);
    }
    __syncthreads();
    find_thresh(hist, scanb, KSEL - above1, &s_bin2, &s_above2, tid);
    unsigned t24 = (bin1 << 12) | s_bin2;      // 24-bit prefix threshold

    // 4) collect candidates: all elements with 24-bit prefix >= threshold prefix.
    //    key = (float_bits << 32) | (16383 - i): descending sort => value desc,
    //    then lower index first (matches jax.lax.top_k tie-break).
    if (tid == 0) s_ncand = 0u;
    __syncthreads();
    for (int i = tid; i < NPB; i += 1024) {
        unsigned u = __float_as_uint(sfg[i]);
        if ((u >> 8) >= t24) {
            unsigned p = atomicAdd(&s_ncand, 1u);
            if (p < SORTN)
                cand[p] = ((u64)u << 32) | (u64)(unsigned)(NPB - 1 - i);
        }
    }
    __syncthreads();
    unsigned nc = s_ncand < SORTN ? s_ncand : SORTN;
    for (int i = tid; i < SORTN; i += 1024)
        if (i >= (int)nc) cand[i] = 0ull;      // pad with smallest key

    // 5) bitonic sort descending (2048 elems, 1024 threads: 1 pair each)
    for (unsigned k = 2; k <= SORTN; k <<= 1) {
        for (unsigned j = k >> 1; j > 0; j >>= 1) {
            __syncthreads();
            unsigned mask = j - 1u;
            unsigned i = ((tid & ~mask) << 1) | (tid & mask);
            unsigned p = i | j;
            u64 a = cand[i], c = cand[p];
            bool desc = ((i & k) == 0u);
            if (desc ? (a < c) : (a > c)) { cand[i] = c; cand[p] = a; }
        }
    }
    __syncthreads();

    // 6) emit top-K local indices
    if (tid < KSEL) {
        unsigned ilocal = (NPB - 1u) - (unsigned)(cand[tid] & 0xFFFFull);
        g_topidx[b * KSEL + tid] = (int)ilocal;
    }
}

// One warp per output row: 20 x float4 scores, 1 x float4 box, batch index.
__global__ void __launch_bounds__(256)
gather_kernel(const float* __restrict__ scores,
              const float* __restrict__ boxes,
              float* __restrict__ out)
{
    int gw   = (blockIdx.x * blockDim.x + threadIdx.x) >> 5;   // global warp = row
    int lane = threadIdx.x & 31;
    if (gw >= BATCH * KSEL) return;

    int b      = gw / KSEL;
    int ilocal = g_topidx[gw];
    size_t g   = (size_t)b * NPB + (size_t)ilocal;

    const float4* srow = (const float4*)(scores + g * NCLS);
    float4*       drow = (float4*)(out + (size_t)gw * NCLS);

    if (lane < 20) {
        drow[lane] = srow[lane];
    } else if (lane == 20) {
        // boxes output block starts after scores [B*K*80] + batch_indices [B*K]
        float4* obox = (float4*)(out + (size_t)BATCH * KSEL * (NCLS + 1));
        obox[gw] = ((const float4*)boxes)[g];
    } else if (lane == 21) {
        // batch_indices block (numeric cast of int -> f32)
        out[(size_t)BATCH * KSEL * NCLS + gw] = (float)b;
    }
}

extern "C" void kernel_launch(void* const* d_in, const int* in_sizes, int n_in,
                              void* d_out, int out_size)
{
    const float* scores = (const float*)d_in[0];
    // d_in[1] = batch_indices (int32): values are exactly row/NPB, recomputed instead
    const float* boxes  = (const float*)d_in[2];
    float* out = (float*)d_out;

    const size_t smem = (size_t)NPB * 4 + (size_t)NBIN * 4 + 1024 * 4 + (size_t)SORTN * 8;
    cudaFuncSetAttribute(topk_kernel, cudaFuncAttributeMaxDynamicSharedMemorySize, (int)smem);

    topk_kernel<<<BATCH, 1024, smem>>>(scores);

    int rows    = BATCH * KSEL;
    int threads = 256;
    int blocks  = (rows * 32 + threads - 1) / threads;
    gather_kernel<<<blocks, threads>>>(scores, boxes, out);
}

// round 2
// speedup vs baseline: 1.2298x; 1.2298x over previous
#include <cuda_runtime.h>
#include <cuda_bf16.h>
#include <stdint.h>

#define BATCH   64
#define NPB     16384
#define KSEL    1000
#define NCLS    80
#define NBIN    4096
#define CANDMAX 2048

typedef unsigned long long u64;

__device__ unsigned g_fg[BATCH * NPB];       // fg float bits per row (4 MB)
__device__ int      g_topidx[BATCH * KSEL];  // selected local indices, rank order

// ---------------------------------------------------------------------------
// Kernel A: strided column-0 read, coalesced write of fg bits.
// 512 CTAs x 256 threads, 2048 rows each. Spread over whole chip.
// ---------------------------------------------------------------------------
__global__ void __launch_bounds__(256)
extract_kernel(const float* __restrict__ scores)
{
    int base = blockIdx.x * 2048;
    int tid  = threadIdx.x;
    #pragma unroll 8
    for (int k = 0; k < 8; k++) {
        int r = base + k * 256 + tid;
        float s = __ldg(scores + (size_t)r * NCLS);
        g_fg[r] = __float_as_uint(1.0f - s);   // positive float: bits are order-preserving
    }
}

// ---------------------------------------------------------------------------
// Kernel B: per-batch exact top-K selection via 2-level radix + rank counting.
// 64 CTAs x 1024 threads, ~96 KB dynamic smem.
// ---------------------------------------------------------------------------
extern __shared__ unsigned char smem_raw[];

// Descending-bin threshold search with warp-shuffle scan (2 barriers).
// tid t owns bins [NBIN-1-4t .. NBIN-4-4t]; ascending tid == descending bins.
__device__ __forceinline__ void find_thresh(
    const unsigned* hist, unsigned Kneed,
    unsigned* out_bin, unsigned* out_above,
    unsigned* warpsums, int tid)
{
    int base = NBIN - 1 - 4 * tid;
    unsigned c0 = hist[base],     c1 = hist[base - 1];
    unsigned c2 = hist[base - 2], c3 = hist[base - 3];
    unsigned tsum = c0 + c1 + c2 + c3;

    unsigned v = tsum;                               // warp inclusive scan
    #pragma unroll
    for (int d = 1; d < 32; d <<= 1) {
        unsigned n = __shfl_up_sync(0xFFFFFFFFu, v, d);
        if ((tid & 31) >= d) v += n;
    }
    if ((tid & 31) == 31) warpsums[tid >> 5] = v;
    __syncthreads();
    if (tid < 32) {
        unsigned w = warpsums[tid];
        #pragma unroll
        for (int d = 1; d < 32; d <<= 1) {
            unsigned n = __shfl_up_sync(0xFFFFFFFFu, w, d);
            if (tid >= d) w += n;
        }
        warpsums[tid] = w;
    }
    __syncthreads();
    unsigned wpre = (tid >= 32) ? warpsums[(tid >> 5) - 1] : 0u;
    unsigned run  = wpre + v - tsum;                 // exclusive prefix (count in higher bins)

    if (run < Kneed && run + c0 >= Kneed) { *out_bin = (unsigned)base;     *out_above = run; }
    run += c0;
    if (run < Kneed && run + c1 >= Kneed) { *out_bin = (unsigned)base - 1; *out_above = run; }
    run += c1;
    if (run < Kneed && run + c2 >= Kneed) { *out_bin = (unsigned)base - 2; *out_above = run; }
    run += c2;
    if (run < Kneed && run + c3 >= Kneed) { *out_bin = (unsigned)base - 3; *out_above = run; }
    __syncthreads();
}

__global__ void __launch_bounds__(1024, 1)
select_kernel()
{
    const int b   = blockIdx.x;
    const int tid = threadIdx.x;

    unsigned* sfg  = (unsigned*)smem_raw;            // 16384 u32 = 64 KB
    unsigned* hist = sfg + NPB;                      //  4096 u32 = 16 KB
    u64*      cand = (u64*)(hist + NBIN);            //  2048 u64 = 16 KB (8B aligned)

    __shared__ unsigned warpsums[32];
    __shared__ unsigned s_bin1, s_above1, s_bin2, s_above2, s_ncand;

    // coalesced reload of fg bits (uint4)
    const uint4* src = (const uint4*)(g_fg + b * NPB);
    uint4* dst = (uint4*)sfg;
    #pragma unroll 4
    for (int i = tid; i < NPB / 4; i += 1024) dst[i] = src[i];

    for (int i = tid; i < NBIN; i += 1024) hist[i] = 0u;
    if (tid == 0) s_ncand = 0u;
    __syncthreads();

    // level-1: top 12 bits
    #pragma unroll 4
    for (int i = tid; i < NPB; i += 1024)
        atomicAdd(&hist[sfg[i] >> 20], 1u);
    __syncthreads();
    find_thresh(hist, KSEL, &s_bin1, &s_above1, warpsums, tid);
    unsigned bin1 = s_bin1, above1 = s_above1;

    // level-2: next 12 bits among elements of bin1
    for (int i = tid; i < NBIN; i += 1024) hist[i] = 0u;
    __syncthreads();
    #pragma unroll 4
    for (int i = tid; i < NPB; i += 1024) {
        unsigned u = sfg[i];
        if ((u >> 20) == bin1) atomicAdd(&hist[(u >> 8) & 0xFFFu], 1u);
    }
    __syncthreads();
    find_thresh(hist, KSEL - above1, &s_bin2, &s_above2, warpsums, tid);
    unsigned t24 = (bin1 << 12) | s_bin2;

    // collect candidates (count >= K, typically ~K+2). key packs value then
    // inverted index so descending key order == value desc, index asc (jax tie-break).
    #pragma unroll 4
    for (int i = tid; i < NPB; i += 1024) {
        unsigned u = sfg[i];
        if ((u >> 8) >= t24) {
            unsigned p = atomicAdd(&s_ncand, 1u);
            if (p < CANDMAX)
                cand[p] = ((u64)u << 32) | (u64)(unsigned)(NPB - 1 - i);
        }
    }
    __syncthreads();
    unsigned nc = s_ncand < CANDMAX ? s_ncand : CANDMAX;

    // exact rank by pairwise counting (keys unique -> ranks unique)
    u64 k0 = (tid < (int)nc)          ? cand[tid]        : 0ull;
    u64 k1 = (tid + 1024 < (int)nc)   ? cand[tid + 1024] : 0ull;
    unsigned r0 = 0, r1 = 0;
    unsigned j = 0;
    for (; j + 4 <= nc; j += 4) {
        u64 c0 = cand[j], c1 = cand[j+1], c2 = cand[j+2], c3 = cand[j+3];
        r0 += (c0 > k0) + (c1 > k0) + (c2 > k0) + (c3 > k0);
        r1 += (c0 > k1) + (c1 > k1) + (c2 > k1) + (c3 > k1);
    }
    for (; j < nc; j++) {
        u64 c = cand[j];
        r0 += (c > k0);
        r1 += (c > k1);
    }
    if (tid < (int)nc && r0 < KSEL)
        g_topidx[b * KSEL + r0] = (int)(NPB - 1u - (unsigned)(k0 & 0xFFFFu));
    if (tid + 1024 < (int)nc && r1 < KSEL)
        g_topidx[b * KSEL + r1] = (int)(NPB - 1u - (unsigned)(k1 & 0xFFFFu));
}

// ---------------------------------------------------------------------------
// Kernel C: gather. Blocks [0,5000): one thread per score float4 chunk.
//           Blocks [5000,5250): boxes (float4) + batch index per row.
// out layout: scores [64000*80] | batch_idx [64000] | boxes [64000*4], all f32.
// ---------------------------------------------------------------------------
__global__ void __launch_bounds__(256)
gather_kernel(const float* __restrict__ scores,
              const float* __restrict__ boxes,
              float* __restrict__ out)
{
    int blk = blockIdx.x;
    if (blk < 5000) {
        int chunk = blk * 256 + threadIdx.x;        // 0 .. 1,279,999 exactly
        int row   = chunk / 20;
        int c     = chunk % 20;
        int il    = g_topidx[row];
        int bb    = row / KSEL;
        size_t g  = (size_t)bb * NPB + (size_t)il;
        float4 v = *(const float4*)(scores + g * NCLS + c * 4);
        *(float4*)(out + (size_t)row * NCLS + c * 4) = v;
    } else {
        int r  = (blk - 5000) * 256 + threadIdx.x;  // 0 .. 63,999 exactly
        int il = g_topidx[r];
        int bb = r / KSEL;
        size_t g = (size_t)bb * NPB + (size_t)il;
        out[(size_t)BATCH * KSEL * NCLS + r] = (float)bb;
        float4 bx = *(const float4*)(boxes + g * 4);
        *(float4*)(out + (size_t)BATCH * KSEL * (NCLS + 1) + (size_t)r * 4) = bx;
    }
}

extern "C" void kernel_launch(void* const* d_in, const int* in_sizes, int n_in,
                              void* d_out, int out_size)
{
    const float* scores = (const float*)d_in[0];
    const float* boxes  = (const float*)d_in[2];
    float* out = (float*)d_out;

    const size_t smemB = (size_t)NPB * 4 + (size_t)NBIN * 4 + (size_t)CANDMAX * 8;
    static int configured = -1;
    if (configured < 0) {
        cudaFuncSetAttribute(select_kernel, cudaFuncAttributeMaxDynamicSharedMemorySize, (int)smemB);
        configured = 1;
    }

    extract_kernel<<<(BATCH * NPB) / 2048, 256>>>(scores);
    select_kernel<<<BATCH, 1024, smemB>>>();
    gather_kernel<<<5250, 256>>>(scores, boxes, out);
}

// round 3
// speedup vs baseline: 1.8535x; 1.5072x over previous
#define _GNU_SOURCE 1
#include <cuda_runtime.h>
#include <cuda.h>
#include <cuda_bf16.h>
#include <stdint.h>
#include <dlfcn.h>

#define BATCH   64
#define NPB     16384
#define KSEL    1000
#define NCLS    80
#define NBIN    4096
#define CANDMAX 2048

typedef unsigned long long u64;

__device__ unsigned g_fg[BATCH * NPB];       // fg float bits per row (4 MB)
__device__ int      g_topidx[BATCH * KSEL];  // selected local indices, rank order

// ---------------------------------------------------------------------------
// Kernel A (TMA path): per CTA load 4 tiles of [8 floats x 256 rows] (32B/row)
// via cp.async.bulk.tensor.2d with L2_PROMOTION_NONE -> sector-granular DRAM.
// ---------------------------------------------------------------------------
__global__ void __launch_bounds__(256)
extract_tma_kernel(const __grid_constant__ CUtensorMap tmap)
{
    __shared__ alignas(128) float tiles[4][2048];   // 4 x 8KB
    __shared__ alignas(8) unsigned long long mbar;

    const int tid  = threadIdx.x;
    const int base = blockIdx.x * 1024;

    unsigned mb = (unsigned)__cvta_generic_to_shared(&mbar);

    if (tid == 0) {
        asm volatile("mbarrier.init.shared.b64 [%0], %1;" :: "r"(mb), "r"(1u) : "memory");
    }
    __syncthreads();

    if (tid == 0) {
        asm volatile("mbarrier.arrive.expect_tx.shared.b64 _, [%0], %1;"
                     :: "r"(mb), "r"(32768u) : "memory");
        #pragma unroll
        for (int t = 0; t < 4; t++) {
            unsigned dst = (unsigned)__cvta_generic_to_shared(&tiles[t][0]);
            int row = base + t * 256;
            asm volatile(
                "cp.async.bulk.tensor.2d.shared::cta.global.tile.mbarrier::complete_tx::bytes "
                "[%0], [%1, {%2, %3}], [%4];"
                :: "r"(dst), "l"(&tmap), "r"(0), "r"(row), "r"(mb) : "memory");
        }
    }

    // wait phase 0
    {
        unsigned done;
        asm volatile(
            "{\n\t.reg .pred p;\n\t"
            "mbarrier.try_wait.parity.acquire.cta.shared::cta.b64 p, [%1], %2;\n\t"
            "selp.b32 %0, 1, 0, p;\n\t}"
            : "=r"(done) : "r"(mb), "r"(0u) : "memory");
        if (!done) {
            asm volatile(
                "{\n\t.reg .pred P1;\n\t"
                "W_%=:\n\t"
                "mbarrier.try_wait.parity.acquire.cta.shared::cta.b64 P1, [%0], %1, 0x989680;\n\t"
                "@P1 bra.uni D_%=;\n\t"
                "bra.uni W_%=;\n\t"
                "D_%=:\n\t}"
                :: "r"(mb), "r"(0u) : "memory");
        }
    }

    #pragma unroll
    for (int t = 0; t < 4; t++) {
        float s = tiles[t][tid * 8];               // col 0 of this row
        g_fg[base + t * 256 + tid] = __float_as_uint(1.0f - s);
    }
}

// ---------------------------------------------------------------------------
// Kernel A (fallback): plain strided LDG version.
// ---------------------------------------------------------------------------
__global__ void __launch_bounds__(256)
extract_ldg_kernel(const float* __restrict__ scores)
{
    int base = blockIdx.x * 2048;
    int tid  = threadIdx.x;
    #pragma unroll 8
    for (int k = 0; k < 8; k++) {
        int r = base + k * 256 + tid;
        float s = __ldg(scores + (size_t)r * NCLS);
        g_fg[r] = __float_as_uint(1.0f - s);
    }
}

// ---------------------------------------------------------------------------
// Kernel B: per-batch top-K. fg bits in registers (16/thread), 2-level radix
// threshold, candidate collect, bitonic sort of 2048 in smem.
// ---------------------------------------------------------------------------
__shared__ unsigned sh_hist[NBIN];      // 16 KB
__shared__ u64      sh_cand[CANDMAX];   // 16 KB
__shared__ unsigned sh_warpsums[32];
__shared__ unsigned s_bin1, s_above1, s_bin2, s_above2, s_ncand;

__device__ __forceinline__ void find_thresh(
    unsigned Kneed, unsigned* out_bin, unsigned* out_above, int tid)
{
    int base = NBIN - 1 - 4 * tid;                 // 4 descending bins per thread
    unsigned c0 = sh_hist[base],     c1 = sh_hist[base - 1];
    unsigned c2 = sh_hist[base - 2], c3 = sh_hist[base - 3];
    unsigned tsum = c0 + c1 + c2 + c3;

    unsigned v = tsum;
    #pragma unroll
    for (int d = 1; d < 32; d <<= 1) {
        unsigned n = __shfl_up_sync(0xFFFFFFFFu, v, d);
        if ((tid & 31) >= d) v += n;
    }
    if ((tid & 31) == 31) sh_warpsums[tid >> 5] = v;
    __syncthreads();
    if (tid < 32) {
        unsigned w = sh_warpsums[tid];
        #pragma unroll
        for (int d = 1; d < 32; d <<= 1) {
            unsigned n = __shfl_up_sync(0xFFFFFFFFu, w, d);
            if (tid >= d) w += n;
        }
        sh_warpsums[tid] = w;
    }
    __syncthreads();
    unsigned wpre = (tid >= 32) ? sh_warpsums[(tid >> 5) - 1] : 0u;
    unsigned run  = wpre + v - tsum;               // count in strictly-higher bins

    if (run < Kneed && run + c0 >= Kneed) { *out_bin = (unsigned)base;     *out_above = run; }
    run += c0;
    if (run < Kneed && run + c1 >= Kneed) { *out_bin = (unsigned)base - 1; *out_above = run; }
    run += c1;
    if (run < Kneed && run + c2 >= Kneed) { *out_bin = (unsigned)base - 2; *out_above = run; }
    run += c2;
    if (run < Kneed && run + c3 >= Kneed) { *out_bin = (unsigned)base - 3; *out_above = run; }
    __syncthreads();
}

__global__ void __launch_bounds__(1024, 1)
select_kernel()
{
    const int b   = blockIdx.x;
    const int tid = threadIdx.x;

    // load 16 fg values into registers (coalesced uint4)
    unsigned v[16];
    const uint4* src = (const uint4*)(g_fg + b * NPB);
    #pragma unroll
    for (int c = 0; c < 4; c++) {
        uint4 x = __ldg(src + c * 1024 + tid);
        v[c * 4 + 0] = x.x; v[c * 4 + 1] = x.y;
        v[c * 4 + 2] = x.z; v[c * 4 + 3] = x.w;
    }

    for (int i = tid; i < NBIN; i += 1024) sh_hist[i] = 0u;
    if (tid == 0) s_ncand = 0u;
    __syncthreads();

    // level-1: top 12 bits
    #pragma unroll
    for (int q = 0; q < 16; q++)
        atomicAdd(&sh_hist[v[q] >> 20], 1u);
    __syncthreads();
    find_thresh(KSEL, &s_bin1, &s_above1, tid);
    unsigned bin1 = s_bin1, above1 = s_above1;

    // level-2: next 12 bits among elements in bin1
    for (int i = tid; i < NBIN; i += 1024) sh_hist[i] = 0u;
    __syncthreads();
    #pragma unroll
    for (int q = 0; q < 16; q++)
        if ((v[q] >> 20) == bin1) atomicAdd(&sh_hist[(v[q] >> 8) & 0xFFFu], 1u);
    __syncthreads();
    find_thresh(KSEL - above1, &s_bin2, &s_above2, tid);
    unsigned t24 = (bin1 << 12) | s_bin2;

    // collect candidates: key = (bits << 32) | (NPB-1-i) so that descending
    // key order == value desc, index asc (jax tie-break).
    #pragma unroll
    for (int c = 0; c < 4; c++) {
        #pragma unroll
        for (int q = 0; q < 4; q++) {
            unsigned u = v[c * 4 + q];
            if ((u >> 8) >= t24) {
                int i = (c * 1024 + tid) * 4 + q;
                unsigned p = atomicAdd(&s_ncand, 1u);
                if (p < CANDMAX)
                    sh_cand[p] = ((u64)u << 32) | (u64)(unsigned)(NPB - 1 - i);
            }
        }
    }
    __syncthreads();
    unsigned nc = s_ncand < CANDMAX ? s_ncand : CANDMAX;
    for (int i = tid; i < CANDMAX; i += 1024)
        if (i >= (int)nc) sh_cand[i] = 0ull;

    // bitonic sort descending, 2048 elems, 1024 threads (1 pair each / stage)
    for (unsigned k = 2; k <= CANDMAX; k <<= 1) {
        for (unsigned j = k >> 1; j > 0; j >>= 1) {
            __syncthreads();
            unsigned mask = j - 1u;
            unsigned i = (((unsigned)tid & ~mask) << 1) | ((unsigned)tid & mask);
            unsigned p = i | j;
            u64 a = sh_cand[i], c = sh_cand[p];
            bool desc = ((i & k) == 0u);
            if (desc ? (a < c) : (a > c)) { sh_cand[i] = c; sh_cand[p] = a; }
        }
    }
    __syncthreads();

    if (tid < KSEL) {
        unsigned ilocal = (NPB - 1u) - (unsigned)(sh_cand[tid] & 0xFFFFull);
        g_topidx[b * KSEL + tid] = (int)ilocal;
    }
}

// ---------------------------------------------------------------------------
// Kernel C: gather with 4 independent row-chunks per thread (MLP 4).
// Blocks [0,1250): scores (4 x float4 chunks each). [1250,1500): boxes+bidx.
// out: scores [64000*80] | batch_idx [64000] | boxes [64000*4], all f32.
// ---------------------------------------------------------------------------
__global__ void __launch_bounds__(256)
gather_kernel(const float* __restrict__ scores,
              const float* __restrict__ boxes,
              float* __restrict__ out)
{
    int blk = blockIdx.x;
    if (blk < 1250) {
        int g0 = blk * 256 + threadIdx.x;           // [0, 320000)
        int   row[4], c[4];
        size_t gsrc[4];
        #pragma unroll
        for (int s = 0; s < 4; s++) {
            int chunk = g0 + s * 320000;            // [0, 1,280,000)
            row[s] = chunk / 20;
            c[s]   = chunk % 20;
            int il = __ldg(&g_topidx[row[s]]);
            int bb = row[s] / KSEL;
            gsrc[s] = (size_t)bb * NPB + (size_t)il;
        }
        float4 val[4];
        #pragma unroll
        for (int s = 0; s < 4; s++)
            val[s] = *(const float4*)(scores + gsrc[s] * NCLS + c[s] * 4);
        #pragma unroll
        for (int s = 0; s < 4; s++)
            *(float4*)(out + (size_t)row[s] * NCLS + c[s] * 4) = val[s];
    } else {
        int r  = (blk - 1250) * 256 + threadIdx.x;  // [0, 64000)
        int il = __ldg(&g_topidx[r]);
        int bb = r / KSEL;
        size_t g = (size_t)bb * NPB + (size_t)il;
        out[(size_t)BATCH * KSEL * NCLS + r] = (float)bb;
        float4 bx = *(const float4*)(boxes + g * 4);
        *(float4*)(out + (size_t)BATCH * KSEL * (NCLS + 1) + (size_t)r * 4) = bx;
    }
}

// ---------------------------------------------------------------------------
typedef CUresult (*EncodeTiledFn)(
    CUtensorMap*, CUtensorMapDataType, cuuint32_t, void*,
    const cuuint64_t*, const cuuint64_t*, const cuuint32_t*, const cuuint32_t*,
    CUtensorMapInterleave, CUtensorMapSwizzle, CUtensorMapL2promotion,
    CUtensorMapFloatOOBfill);

extern "C" void kernel_launch(void* const* d_in, const int* in_sizes, int n_in,
                              void* d_out, int out_size)
{
    const float* scores = (const float*)d_in[0];
    const float* boxes  = (const float*)d_in[2];
    float* out = (float*)d_out;

    // --- extract: TMA path if driver symbol is reachable, else LDG fallback
    bool tma_ok = false;
    alignas(64) CUtensorMap tmap;
    EncodeTiledFn enc = (EncodeTiledFn)dlsym(RTLD_DEFAULT, "cuTensorMapEncodeTiled");
    if (enc) {
        cuuint64_t dims[2]    = { (cuuint64_t)NCLS, (cuuint64_t)(BATCH * NPB) };
        cuuint64_t strides[1] = { (cuuint64_t)NCLS * sizeof(float) };   // 320 B
        cuuint32_t box[2]     = { 8, 256 };                             // 32 B x 256 rows
        cuuint32_t es[2]      = { 1, 1 };
        CUresult r = enc(&tmap, CU_TENSOR_MAP_DATA_TYPE_FLOAT32, 2, (void*)scores,
                         dims, strides, box, es,
                         CU_TENSOR_MAP_INTERLEAVE_NONE, CU_TENSOR_MAP_SWIZZLE_NONE,
                         CU_TENSOR_MAP_L2_PROMOTION_NONE, CU_TENSOR_MAP_FLOAT_OOB_FILL_NONE);
        tma_ok = (r == CUDA_SUCCESS);
    }

    if (tma_ok)
        extract_tma_kernel<<<(BATCH * NPB) / 1024, 256>>>(tmap);
    else
        extract_ldg_kernel<<<(BATCH * NPB) / 2048, 256>>>(scores);

    select_kernel<<<BATCH, 1024>>>();
    gather_kernel<<<1500, 256>>>(scores, boxes, out);
}